// round 5
// baseline (speedup 1.0000x reference)
#include <cuda_runtime.h>
#include <stdint.h>
#include <math.h>

// ---------------------------------------------------------------------------
// DetectionTargetLayer (Mask R-CNN) — exact replication of the JAX reference.
// Threefry-2x32 PRNG (partitionable). XLA AlgebraicSimplifier rewrites:
//   x/const -> x * rn(1/const);  mul(mul(x,c1),c2) -> mul(x, rn(c1*c2)).
// So mask step = (y2-y1) * rn(1023/27) in ONE multiply, deltas use *10 / *5.
// ---------------------------------------------------------------------------

#define JAX_PARTITIONABLE 1

#define BB     2
#define NPROP  2000
#define NGT    50
#define TRAIN  200
#define PCAP   66
#define NCAP   134
#define MH     28
#define MW     28
#define IMH    1024
#define IMW    1024
#define SORTN  2048

#define ROIS_OFF 0
#define CLS_OFF  (BB*TRAIN*4)
#define DELT_OFF (CLS_OFF + BB*TRAIN)
#define MASK_OFF (DELT_OFF + BB*TRAIN*4)

#define NEG_RATIO_F ((float)(1.0/0.33))   // np.float32(1.0/ROI_POS_RATIO)
#define STEPC (1023.0f / 27.0f)           // folded constant rn(1023/27)

struct Keys { uint32_t kp0[BB], kp1[BB], kn0[BB], kn1[BB]; };

__host__ __device__ __forceinline__ uint32_t rotl32(uint32_t v, int r) {
    return (v << r) | (v >> (32 - r));
}

__host__ __device__ __forceinline__ void threefry2x32(
    uint32_t k0, uint32_t k1, uint32_t x0, uint32_t x1,
    uint32_t* o0, uint32_t* o1)
{
    uint32_t ks2 = k0 ^ k1 ^ 0x1BD11BDAu;
    x0 += k0; x1 += k1;
#define TF_R(r) { x0 += x1; x1 = rotl32(x1, (r)); x1 ^= x0; }
    TF_R(13) TF_R(15) TF_R(26) TF_R(6)   x0 += k1;  x1 += ks2 + 1u;
    TF_R(17) TF_R(29) TF_R(16) TF_R(24)  x0 += ks2; x1 += k0 + 2u;
    TF_R(13) TF_R(15) TF_R(26) TF_R(6)   x0 += k0;  x1 += k1 + 3u;
    TF_R(17) TF_R(29) TF_R(16) TF_R(24)  x0 += k1;  x1 += ks2 + 4u;
    TF_R(13) TF_R(15) TF_R(26) TF_R(6)   x0 += ks2; x1 += k0 + 5u;
#undef TF_R
    *o0 = x0; *o1 = x1;
}

__device__ __forceinline__ float bits_to_uniform(uint32_t bits) {
    return __uint_as_float((bits >> 9) | 0x3f800000u) - 1.0f;
}

__device__ __forceinline__ float uniform_at(uint32_t k0, uint32_t k1, int i) {
#if JAX_PARTITIONABLE
    uint32_t o0, o1;
    threefry2x32(k0, k1, 0u, (uint32_t)i, &o0, &o1);
    return bits_to_uniform(o0 ^ o1);
#else
    uint32_t o0, o1;
    if (i < NPROP / 2) {
        threefry2x32(k0, k1, (uint32_t)i, (uint32_t)(i + NPROP / 2), &o0, &o1);
        return bits_to_uniform(o0);
    } else {
        threefry2x32(k0, k1, (uint32_t)(i - NPROP / 2), (uint32_t)i, &o0, &o1);
        return bits_to_uniform(o1);
    }
#endif
}

__device__ __forceinline__ float iou_f(
    float ay1, float ax1, float ay2, float ax2,
    float by1, float bx1, float by2, float bx2)
{
    float ih = fmaxf(fminf(ay2, by2) - fmaxf(ay1, by1), 0.0f);
    float iw = fmaxf(fminf(ax2, bx2) - fmaxf(ax1, bx1), 0.0f);
    float inter = __fmul_rn(ih, iw);
    float a1 = __fmul_rn(ay2 - ay1, ax2 - ax1);
    float a2 = __fmul_rn(by2 - by1, bx2 - bx1);
    float uni = (a1 + a2) - inter;
    return (uni > 0.0f) ? __fdiv_rn(inter, uni) : 0.0f;   // non-const denom: stays div
}

// staging between kernels
__device__ float g_pos_rois[BB][PCAP][4];
__device__ int   g_assign[BB][PCAP];
__device__ int   g_p[BB];

// Full descending bitonic sort (value desc, idx asc — matches lax.top_k).
__device__ void bitonic_sort_desc(float* val, int* idx) {
    for (int k = 2; k <= SORTN; k <<= 1) {
        for (int j = k >> 1; j > 0; j >>= 1) {
            __syncthreads();
            for (int t = threadIdx.x; t < SORTN; t += blockDim.x) {
                int l = t ^ j;
                if (l > t) {
                    float va = val[t], vb = val[l];
                    int   ia = idx[t], ib = idx[l];
                    bool a_first = (va > vb) || (va == vb && ia < ib);
                    bool desc = ((t & k) == 0);
                    bool keep = desc ? a_first : !a_first;
                    if (!keep) {
                        val[t] = vb; val[l] = va;
                        idx[t] = ib; idx[l] = ia;
                    }
                }
            }
        }
    }
    __syncthreads();
}

__global__ __launch_bounds__(1024)
void dtl_main(const float* __restrict__ proposals,
              const int*   __restrict__ gt_class_ids,
              const float* __restrict__ gt_boxes,
              float* __restrict__ out,
              Keys keys)
{
    const int b   = blockIdx.x;
    const int tid = threadIdx.x;

    __shared__ float s_gt[NGT][4];
    __shared__ int   s_cls[NGT];
    __shared__ int   s_noncrowd[NGT];
    __shared__ int   s_crowd[NGT];
    __shared__ float s_pscore[NPROP];
    __shared__ float s_nscore[NPROP];
    __shared__ float s_val[SORTN];
    __shared__ int   s_idx[SORTN];
    __shared__ int   s_pidx[PCAP];
    __shared__ int   s_nidx[NCAP];
    __shared__ int   s_cpos, s_cneg;

    if (tid == 0) { s_cpos = 0; s_cneg = 0; }
    if (tid < NGT) {
        float g0 = gt_boxes[((size_t)b * NGT + tid) * 4 + 0];
        float g1 = gt_boxes[((size_t)b * NGT + tid) * 4 + 1];
        float g2 = gt_boxes[((size_t)b * NGT + tid) * 4 + 2];
        float g3 = gt_boxes[((size_t)b * NGT + tid) * 4 + 3];
        s_gt[tid][0] = g0; s_gt[tid][1] = g1; s_gt[tid][2] = g2; s_gt[tid][3] = g3;
        int valid = (fabsf(g0) + fabsf(g1) + fabsf(g2) + fabsf(g3)) > 0.0f;
        int cls = gt_class_ids[(size_t)b * NGT + tid];
        s_cls[tid] = cls;
        s_noncrowd[tid] = (cls > 0) && valid;
        s_crowd[tid]    = (cls < 0) && valid;
    }
    __syncthreads();

    // -------- phase A: per-proposal IoU stats + masked uniform scores -----
    for (int i = tid; i < NPROP; i += blockDim.x) {
        const float* pr = proposals + ((size_t)b * NPROP + i) * 4;
        float py1 = pr[0], px1 = pr[1], py2 = pr[2], px2 = pr[3];
        bool valid = (fabsf(py1) + fabsf(px1) + fabsf(py2) + fabsf(px2)) > 0.0f;
        float rmax = -1.0f, cmax = -1.0f;
        #pragma unroll 5
        for (int g = 0; g < NGT; ++g) {
            float v = iou_f(py1, px1, py2, px2,
                            s_gt[g][0], s_gt[g][1], s_gt[g][2], s_gt[g][3]);
            if (s_noncrowd[g]) rmax = fmaxf(rmax, v);
            if (s_crowd[g])    cmax = fmaxf(cmax, v);
        }
        bool pos = valid && (rmax >= 0.5f);
        bool neg = valid && (rmax < 0.5f) && (cmax < 1e-3f);
        s_pscore[i] = pos ? uniform_at(keys.kp0[b], keys.kp1[b], i) : -1.0f;
        s_nscore[i] = neg ? uniform_at(keys.kn0[b], keys.kn1[b], i) : -1.0f;
        if (pos) atomicAdd(&s_cpos, 1);
        if (neg) atomicAdd(&s_cneg, 1);
    }
    __syncthreads();

    // -------- positive top-k (full sort) ---------------------------------
    for (int t = tid; t < SORTN; t += blockDim.x) {
        s_val[t] = (t < NPROP) ? s_pscore[t] : -1.0f;
        s_idx[t] = t;
    }
    bitonic_sort_desc(s_val, s_idx);
    if (tid < PCAP) s_pidx[tid] = s_idx[tid];
    __syncthreads();

    // -------- negative top-k ---------------------------------------------
    for (int t = tid; t < SORTN; t += blockDim.x) {
        s_val[t] = (t < NPROP) ? s_nscore[t] : -1.0f;
        s_idx[t] = t;
    }
    bitonic_sort_desc(s_val, s_idx);
    if (tid < NCAP) s_nidx[tid] = s_idx[tid];
    __syncthreads();

    const int p = min(s_cpos, PCAP);
    const int needed = (int)(NEG_RATIO_F * (float)p) - p;
    const int n = min(min(s_cneg, needed), NCAP);

    float* rois_o = out + ROIS_OFF + (size_t)b * TRAIN * 4;
    float* cls_o  = out + CLS_OFF  + (size_t)b * TRAIN;
    float* del_o  = out + DELT_OFF + (size_t)b * TRAIN * 4;

    for (int t = tid; t < TRAIN * 4; t += blockDim.x) { rois_o[t] = 0.0f; del_o[t] = 0.0f; }
    for (int t = tid; t < TRAIN;     t += blockDim.x) { cls_o[t] = 0.0f; }
    __syncthreads();

    // -------- positives: rois, class, deltas, staging for masks ----------
    if (tid < PCAP) {
        const int j = tid;
        const bool take = j < p;
        int i = s_pidx[j];
        if (i >= NPROP) i = 0;
        const float* pr = proposals + ((size_t)b * NPROP + i) * 4;
        float ry1 = pr[0], rx1 = pr[1], ry2 = pr[2], rx2 = pr[3];

        int a = 0; float best = -1.0f;
        for (int g = 0; g < NGT; ++g) {
            float ov = s_noncrowd[g]
                     ? iou_f(ry1, rx1, ry2, rx2,
                             s_gt[g][0], s_gt[g][1], s_gt[g][2], s_gt[g][3])
                     : -1.0f;
            if (ov > best) { best = ov; a = g; }
        }

        if (take) {
            rois_o[j * 4 + 0] = ry1; rois_o[j * 4 + 1] = rx1;
            rois_o[j * 4 + 2] = ry2; rois_o[j * 4 + 3] = rx2;

            float h  = ry2 - ry1,  w  = rx2 - rx1;
            float cy = ry1 + 0.5f * h, cx = rx1 + 0.5f * w;
            float gy1 = s_gt[a][0], gx1 = s_gt[a][1], gy2 = s_gt[a][2], gx2 = s_gt[a][3];
            float gh = gy2 - gy1, gw = gx2 - gx1;
            float gcy = gy1 + 0.5f * gh, gcx = gx1 + 0.5f * gw;
            // XLA: divide-by-constant -> multiply-by-reciprocal (10.0f, 5.0f)
            del_o[j * 4 + 0] = __fmul_rn(__fdiv_rn(gcy - cy, h), 10.0f);
            del_o[j * 4 + 1] = __fmul_rn(__fdiv_rn(gcx - cx, w), 10.0f);
            del_o[j * 4 + 2] = __fmul_rn(logf(__fdiv_rn(gh, h)), 5.0f);
            del_o[j * 4 + 3] = __fmul_rn(logf(__fdiv_rn(gw, w)), 5.0f);

            cls_o[j] = (float)s_cls[a];

            g_pos_rois[b][j][0] = ry1; g_pos_rois[b][j][1] = rx1;
            g_pos_rois[b][j][2] = ry2; g_pos_rois[b][j][3] = rx2;
            g_assign[b][j] = a;
        }
    }

    // -------- negatives: rois rows [p, p+n) ------------------------------
    if (tid >= 256 && tid < 256 + NCAP) {
        const int j = tid - 256;
        if (j < n) {
            int i = s_nidx[j];
            if (i >= NPROP) i = 0;
            const float* pr = proposals + ((size_t)b * NPROP + i) * 4;
            const int row = p + j;
            rois_o[row * 4 + 0] = pr[0]; rois_o[row * 4 + 1] = pr[1];
            rois_o[row * 4 + 2] = pr[2]; rois_o[row * 4 + 3] = pr[3];
        }
    }

    if (tid == 0) g_p[b] = p;
}

// ---------------------------------------------------------------------------
// Kernel 2: masks. step = (y2-y1) * rn(1023/27) — ONE multiply (XLA folded).
// Coordinates combined with plain mul/add (no-contract emission).
// ---------------------------------------------------------------------------
__global__ __launch_bounds__(256)
void dtl_masks(const float* __restrict__ gt_masks, float* __restrict__ out)
{
    const int b = blockIdx.y;
    const int j = blockIdx.x;
    const int tid = threadIdx.x;
    float* mo = out + MASK_OFF + ((size_t)(b * TRAIN + j)) * (MH * MW);

    const int p = g_p[b];
    if (j >= p) {
        for (int t = tid; t < MH * MW; t += blockDim.x) mo[t] = 0.0f;
        return;
    }

    __shared__ int   sy0[MH], sy1[MH], svy[MH];
    __shared__ float swy[MH];
    __shared__ int   sx0[MW], sx1[MW], svx[MW];
    __shared__ float swx[MW];
    __shared__ float box[4];
    __shared__ int   sg;

    if (tid < 4) box[tid] = g_pos_rois[b][j][tid];
    if (tid == 4) sg = g_assign[b][j];
    __syncthreads();

    const float y1 = box[0], x1 = box[1], y2 = box[2], x2 = box[3];

    if (tid < MH) {
        float base = __fmul_rn(y1, 1023.0f);
        float step = __fmul_rn(y2 - y1, STEPC);                    // folded const
        float fy   = __fadd_rn(base, __fmul_rn((float)tid, step)); // plain mul+add
        float f0 = floorf(fy);
        swy[tid] = fy - f0;
        sy0[tid] = (int)fminf(fmaxf(f0, 0.0f), 1023.0f);
        sy1[tid] = (int)fminf(fmaxf(f0 + 1.0f, 0.0f), 1023.0f);
        svy[tid] = (fy >= 0.0f) && (fy <= 1023.0f);
    } else if (tid >= 32 && tid < 32 + MW) {
        int c = tid - 32;
        float base = __fmul_rn(x1, 1023.0f);
        float step = __fmul_rn(x2 - x1, STEPC);
        float fx   = __fadd_rn(base, __fmul_rn((float)c, step));
        float f0 = floorf(fx);
        swx[c] = fx - f0;
        sx0[c] = (int)fminf(fmaxf(f0, 0.0f), 1023.0f);
        sx1[c] = (int)fminf(fmaxf(f0 + 1.0f, 0.0f), 1023.0f);
        svx[c] = (fx >= 0.0f) && (fx <= 1023.0f);
    }
    __syncthreads();

    const int g = sg;
    for (int pix = tid; pix < MH * MW; pix += blockDim.x) {
        int r = pix / MW, c = pix % MW;
        if (!(svy[r] && svx[c])) { mo[pix] = 0.0f; continue; }
        size_t rb0 = ((size_t)(b * IMH + sy0[r])) * IMW;
        size_t rb1 = ((size_t)(b * IMH + sy1[r])) * IMW;
        float m00 = gt_masks[(rb0 + sx0[c]) * NGT + g];
        float m01 = gt_masks[(rb0 + sx1[c]) * NGT + g];
        float m10 = gt_masks[(rb1 + sx0[c]) * NGT + g];
        float m11 = gt_masks[(rb1 + sx1[c]) * NGT + g];
        float wx = swx[c], wy = swy[r];
        float omwx = 1.0f - wx, omwy = 1.0f - wy;
        float top = __fadd_rn(__fmul_rn(m00, omwx), __fmul_rn(m01, wx));
        float bot = __fadd_rn(__fmul_rn(m10, omwx), __fmul_rn(m11, wx));
        float v   = __fadd_rn(__fmul_rn(top, omwy), __fmul_rn(bot, wy));
        mo[pix] = rintf(v);   // round half to even
    }
}

// ---------------------------------------------------------------------------
static void compute_keys(Keys* K) {
#if JAX_PARTITIONABLE
    for (int b = 0; b < BB; b++) {
        uint32_t kb0, kb1;
        threefry2x32(0u, 42u, 0u, (uint32_t)b, &kb0, &kb1);
        threefry2x32(kb0, kb1, 0u, 0u, &K->kp0[b], &K->kp1[b]);
        threefry2x32(kb0, kb1, 0u, 1u, &K->kn0[b], &K->kn1[b]);
    }
#else
    uint32_t a0, b0, a1, b1;
    threefry2x32(0u, 42u, 0u, 2u, &a0, &b0);
    threefry2x32(0u, 42u, 1u, 3u, &a1, &b1);
    uint32_t kb[BB][2] = { { a0, a1 }, { b0, b1 } };
    for (int b = 0; b < BB; b++) {
        uint32_t c0, d0, c1, d1;
        threefry2x32(kb[b][0], kb[b][1], 0u, 2u, &c0, &d0);
        threefry2x32(kb[b][0], kb[b][1], 1u, 3u, &c1, &d1);
        K->kp0[b] = c0; K->kp1[b] = c1;
        K->kn0[b] = d0; K->kn1[b] = d1;
    }
#endif
}

extern "C" void kernel_launch(void* const* d_in, const int* in_sizes, int n_in,
                              void* d_out, int out_size)
{
    const float* proposals    = (const float*)d_in[0];
    const int*   gt_class_ids = (const int*)d_in[1];
    const float* gt_boxes     = (const float*)d_in[2];
    const float* gt_masks     = (const float*)d_in[3];
    float* out = (float*)d_out;

    Keys keys;
    compute_keys(&keys);

    dtl_main<<<BB, 1024>>>(proposals, gt_class_ids, gt_boxes, out, keys);
    dtl_masks<<<dim3(TRAIN, BB), 256>>>(gt_masks, out);
}